// round 1
// baseline (speedup 1.0000x reference)
#include <cuda_runtime.h>
#include <cuda_bf16.h>
#include <cstdint>

// KronLinear: out[n, a2*64+b2] = sum_r sum_a sum_b x[n,a*64+b]*A[r,a,a2]*B'[r,b,b2] + bias
//   B'[r,b,b2] = B[(r*64+b2)%4, b, (r*64+b2)/4]
// Fused two-stage tf32 tensor-core kernel, persistent CTAs, weights in smem.

#define LDX 68    // Xs [64][68]      (also output staging)
#define LDB 264   // Bs [64][264]     Bs[b][c]
#define LDA 260   // AsT [64][260]    AsT[a2][k], k = r*64+a
#define LDT 264   // T  [64][264]     T[a][c]

#define SMEM_FLOATS (64*LDB + 64*LDA + 64*LDT + 64*LDX)

__device__ __forceinline__ float tf32r(float f) {
    uint32_t u;
    asm("cvt.rna.tf32.f32 %0, %1;" : "=r"(u) : "f"(f));
    return __uint_as_float(u);
}

__device__ __forceinline__ void mma_tf32(float c[4], const uint32_t a[4], const uint32_t b[2]) {
    asm volatile(
        "mma.sync.aligned.m16n8k8.row.col.f32.tf32.tf32.f32 "
        "{%0,%1,%2,%3}, {%4,%5,%6,%7}, {%8,%9}, {%0,%1,%2,%3};"
        : "+f"(c[0]), "+f"(c[1]), "+f"(c[2]), "+f"(c[3])
        : "r"(a[0]), "r"(a[1]), "r"(a[2]), "r"(a[3]), "r"(b[0]), "r"(b[1]));
}

__global__ void __launch_bounds__(256, 1)
kron_kernel(const float* __restrict__ x, const float* __restrict__ A,
            const float* __restrict__ B, const float* __restrict__ bias,
            float* __restrict__ out, int n_tok)
{
    extern __shared__ float sm[];
    float* Bs  = sm;                    // 64 x LDB
    float* AsT = Bs  + 64 * LDB;        // 64 x LDA
    float* T   = AsT + 64 * LDA;        // 64 x LDT
    float* Xs  = T   + 64 * LDT;        // 64 x LDX

    const int tid  = threadIdx.x;
    const int lane = tid & 31;
    const int w    = tid >> 5;          // 8 warps
    const int g    = lane >> 2;         // group id 0..7
    const int tig  = lane & 3;          // thread in group 0..3

    // ---- Build tf32-rounded weight matrices in smem (once per CTA) ----
    for (int i = tid; i < 64 * 256; i += 256) {
        int row = i >> 8;               // b for Bs, a2 for AsT
        int c   = i & 255;              // c for Bs, k for AsT
        // Bs[b][c] = B[c%4][b][c/4]
        Bs[row * LDB + c] = tf32r(B[(c & 3) * 4096 + row * 64 + (c >> 2)]);
        // AsT[a2][k] = A[k/64][k%64][a2]
        AsT[row * LDA + c] = tf32r(A[(c >> 6) * 4096 + (c & 63) * 64 + row]);
    }
    __syncthreads();

    for (int tok = blockIdx.x; tok < n_tok; tok += gridDim.x) {
        // ---- Load x token (64x64) into Xs, tf32-rounded, coalesced float4 ----
        const float4* xin = (const float4*)(x + (size_t)tok * 4096);
        #pragma unroll
        for (int it = 0; it < 4; it++) {
            int i = tid + it * 256;     // 0..1023
            float4 v = xin[i];
            int a = i >> 4;
            int b = (i & 15) * 4;
            float* dst = &Xs[a * LDX + b];
            dst[0] = tf32r(v.x); dst[1] = tf32r(v.y);
            dst[2] = tf32r(v.z); dst[3] = tf32r(v.w);
        }
        __syncthreads();

        // ---- Stage 1: T[a][c] = sum_b Xs[a][b] * Bs[b][c] ----
        // warp w covers c in [w*32, w*32+32): 4 n-tiles of 8; M=64 -> 4 m-tiles; K=64
        {
            const int n0 = w * 32;
            float acc[4][4][4];
            #pragma unroll
            for (int mi = 0; mi < 4; mi++)
                #pragma unroll
                for (int ni = 0; ni < 4; ni++)
                    #pragma unroll
                    for (int r = 0; r < 4; r++) acc[mi][ni][r] = 0.0f;

            #pragma unroll
            for (int k0 = 0; k0 < 64; k0 += 8) {
                uint32_t af[4][4];
                #pragma unroll
                for (int mi = 0; mi < 4; mi++) {
                    const float* base = &Xs[(mi * 16 + g) * LDX + k0 + tig];
                    af[mi][0] = __float_as_uint(base[0]);
                    af[mi][1] = __float_as_uint(base[8 * LDX]);
                    af[mi][2] = __float_as_uint(base[4]);
                    af[mi][3] = __float_as_uint(base[8 * LDX + 4]);
                }
                uint32_t bf[4][2];
                #pragma unroll
                for (int ni = 0; ni < 4; ni++) {
                    bf[ni][0] = __float_as_uint(Bs[(k0 + tig)     * LDB + n0 + ni * 8 + g]);
                    bf[ni][1] = __float_as_uint(Bs[(k0 + tig + 4) * LDB + n0 + ni * 8 + g]);
                }
                #pragma unroll
                for (int mi = 0; mi < 4; mi++)
                    #pragma unroll
                    for (int ni = 0; ni < 4; ni++)
                        mma_tf32(acc[mi][ni], af[mi], bf[ni]);
            }
            // write T (tf32-rounded for stage 2)
            #pragma unroll
            for (int mi = 0; mi < 4; mi++) {
                int row = mi * 16 + g;
                #pragma unroll
                for (int ni = 0; ni < 4; ni++) {
                    int col = n0 + ni * 8 + 2 * tig;
                    T[row * LDT + col]           = tf32r(acc[mi][ni][0]);
                    T[row * LDT + col + 1]       = tf32r(acc[mi][ni][1]);
                    T[(row + 8) * LDT + col]     = tf32r(acc[mi][ni][2]);
                    T[(row + 8) * LDT + col + 1] = tf32r(acc[mi][ni][3]);
                }
            }
        }
        __syncthreads();

        // ---- Stage 2: out[a2][b2] = sum_k AsT[a2][k] * T2[k][b2],
        //      T2[k][b2] = T[k&63][(k>>6)*64 + b2] ----
        // warp w covers b2 in [w*8, w*8+8): 1 n-tile; M=64 -> 4 m-tiles; K=256
        {
            const int n0 = w * 8;
            float acc[4][4];
            #pragma unroll
            for (int mi = 0; mi < 4; mi++)
                #pragma unroll
                for (int r = 0; r < 4; r++) acc[mi][r] = 0.0f;

            #pragma unroll 4
            for (int k0 = 0; k0 < 256; k0 += 8) {
                const int roff = (k0 >> 6) * 64;
                const int a0   = k0 & 63;
                uint32_t bf[2];
                bf[0] = __float_as_uint(T[(a0 + tig)     * LDT + roff + n0 + g]);
                bf[1] = __float_as_uint(T[(a0 + tig + 4) * LDT + roff + n0 + g]);
                #pragma unroll
                for (int mi = 0; mi < 4; mi++) {
                    uint32_t af[4];
                    const float* base = &AsT[(mi * 16 + g) * LDA + k0 + tig];
                    af[0] = __float_as_uint(base[0]);
                    af[1] = __float_as_uint(base[8 * LDA]);
                    af[2] = __float_as_uint(base[4]);
                    af[3] = __float_as_uint(base[8 * LDA + 4]);
                    mma_tf32(acc[mi], af, bf);
                }
            }
            // stage to Xs (fp32) for coalesced output
            #pragma unroll
            for (int mi = 0; mi < 4; mi++) {
                int row = mi * 16 + g;
                int col = n0 + 2 * tig;
                Xs[row * LDX + col]           = acc[mi][0];
                Xs[row * LDX + col + 1]       = acc[mi][1];
                Xs[(row + 8) * LDX + col]     = acc[mi][2];
                Xs[(row + 8) * LDX + col + 1] = acc[mi][3];
            }
        }
        __syncthreads();

        // ---- Coalesced output + bias ----
        float* orow = out + (size_t)tok * 4096;
        #pragma unroll
        for (int it = 0; it < 16; it++) {
            int i = tid + it * 256;
            orow[i] = Xs[(i >> 6) * LDX + (i & 63)] + bias[i];
        }
        __syncthreads();   // Xs reused next iteration
    }
}

extern "C" void kernel_launch(void* const* d_in, const int* in_sizes, int n_in,
                              void* d_out, int out_size) {
    const float* x    = (const float*)d_in[0];
    const float* A    = (const float*)d_in[1];
    const float* B    = (const float*)d_in[2];
    const float* bias = (const float*)d_in[3];
    float* out = (float*)d_out;

    int n_tok = in_sizes[0] / 4096;

    int dev = 0, nsm = 148;
    cudaGetDevice(&dev);
    cudaDeviceGetAttribute(&nsm, cudaDevAttrMultiProcessorCount, dev);

    size_t smem = SMEM_FLOATS * sizeof(float);
    cudaFuncSetAttribute(kron_kernel, cudaFuncAttributeMaxDynamicSharedMemorySize, (int)smem);

    int grid = nsm < n_tok ? nsm : n_tok;
    kron_kernel<<<grid, 256, smem>>>(x, A, B, bias, out, n_tok);
}

// round 4
// speedup vs baseline: 2.1423x; 2.1423x over previous
#include <cuda_runtime.h>
#include <cstdint>

// ============================================================================
// KronLinear via tcgen05 (sm_103a), kind::tf32, SS-mode, TMEM accumulators.
//
// Per 2-token group:
//   Stage1: D1[(tok,a)][(r,b2)] = sum_b X[(tok,a)][b] * Bs'[(r,b2)][b]
//           M=128, N=256 (2 x N=128 MMAs), K=64  (8 tf32 K-steps per N-half)
//   Shuffle: D1 (TMEM) -> rna(tf32) -> S2A[(tok,b2)][a] per r-chunk (SMEM)
//   Stage2: D2[(tok,b2)][a2] = sum_k S2A[(tok,b2)][k] * AsT[a2][k]
//           M=128, N=64, K=256 (4 r-chunks of K=64, double-buffered)
//   Epilogue: D2 -> SMEM transpose -> out + bias (bias in registers)
//
// The tcgen05 path is guarded to the arch-specific (sm_103a) compilation pass;
// the generic compute_103 PTX pass gets a correct plain-FMA fallback so all
// ptxas passes compile. At runtime the exact-match sm_103a SASS is used.
// ============================================================================

#if defined(__CUDA_ARCH_FEAT_SM103_ALL) || defined(__CUDA_ARCH_FEAT_SM100_ALL) || \
    defined(__CUDA_ARCH_FEAT_SM101_ALL) || defined(__CUDA_ARCH_SPECIFIC__)
#define KRON_TCGEN05 1
#endif

#define OFF_X    0         // 2 K-tiles x [128 rows][32 f32] = 2 x 16KB
#define OFF_BST  32768     // 2 K-tiles x [256 rows][32 f32] = 2 x 32KB
#define OFF_AST  98304     // 8 K-tiles x [ 64 rows][32 f32] = 8 x 8KB
#define OFF_S2A  163840    // 2 bufs x 2 K-tiles x [128][32] = 64KB ; also epi staging
#define OFF_HDR  229376    // +0 tmem ptr, +8/+16/+24 mbarriers
#define SMEM_TOTAL (229376 + 128)

#define SWZ(o) ((o) ^ (((o) >> 3) & 0x70))

// idesc (kind::f16-family layout): [4:6) dtype F32=1, [7:10) atype TF32=2,
// [10:13) btype TF32=2, [17:22) N>>3, [24:29) M>>4
#define IDESC1 ((1u<<4)|(2u<<7)|(2u<<10)|((128u/8)<<17)|((128u/16)<<24))   // M128 N128
#define IDESC2 ((1u<<4)|(2u<<7)|(2u<<10)|(( 64u/8)<<17)|((128u/16)<<24))   // M128 N64

__device__ __forceinline__ uint32_t cvta_smem(const void* p) {
    uint32_t a;
    asm("{ .reg .u64 t; cvta.to.shared.u64 t, %1; cvt.u32.u64 %0, t; }" : "=r"(a) : "l"(p));
    return a;
}
__device__ __forceinline__ uint32_t tf32u(float f) {
    uint32_t u; asm("cvt.rna.tf32.f32 %0, %1;" : "=r"(u) : "f"(f)); return u;
}
__device__ __forceinline__ void sts32(uint32_t a, uint32_t v) {
    asm volatile("st.shared.b32 [%0], %1;" :: "r"(a), "r"(v) : "memory");
}
__device__ __forceinline__ void sts128(uint32_t a, uint32_t x, uint32_t y, uint32_t z, uint32_t w) {
    asm volatile("st.shared.v4.b32 [%0], {%1,%2,%3,%4};" :: "r"(a), "r"(x), "r"(y), "r"(z), "r"(w) : "memory");
}
__device__ __forceinline__ float lds32f(uint32_t a) {
    float v; asm volatile("ld.shared.f32 %0, [%1];" : "=f"(v) : "r"(a)); return v;
}

#ifdef KRON_TCGEN05

__device__ __forceinline__ void mbar_init(uint32_t a, uint32_t c) {
    asm volatile("mbarrier.init.shared.b64 [%0], %1;" :: "r"(a), "r"(c) : "memory");
}
__device__ __forceinline__ void mbar_wait(uint32_t a, uint32_t parity) {
    asm volatile(
        "{\n\t.reg .pred P;\n\t"
        "WL_%=:\n\t"
        "mbarrier.try_wait.parity.acquire.cta.shared::cta.b64 P, [%0], %1, 0x989680;\n\t"
        "@P bra.uni WD_%=;\n\t"
        "bra.uni WL_%=;\n\t"
        "WD_%=:\n\t}"
        :: "r"(a), "r"(parity) : "memory");
}

#define TC_ALLOC(sa, n)   asm volatile("tcgen05.alloc.cta_group::1.sync.aligned.shared::cta.b32 [%0], %1;" :: "r"(sa), "r"((uint32_t)(n)) : "memory")
#define TC_DEALLOC(t, n)  asm volatile("tcgen05.dealloc.cta_group::1.sync.aligned.b32 %0, %1;" :: "r"(t), "r"((uint32_t)(n)))
#define TC_WAIT_LD()      asm volatile("tcgen05.wait::ld.sync.aligned;" ::: "memory")
#define TC_FENCE_BEFORE() asm volatile("tcgen05.fence::before_thread_sync;" ::: "memory")
#define TC_FENCE_AFTER()  asm volatile("tcgen05.fence::after_thread_sync;" ::: "memory")
#define TC_COMMIT(mb)     asm volatile("tcgen05.commit.cta_group::1.mbarrier::arrive::one.shared::cluster.b64 [%0];" :: "r"(mb) : "memory")
#define FENCE_ASYNC()     asm volatile("fence.proxy.async.shared::cta;" ::: "memory")

__device__ __forceinline__ uint64_t sdesc(uint32_t addr) {  // SW128, version=1, SBO=64, LBO=1
    return (uint64_t(2) << 61) | (uint64_t(1) << 46) | (uint64_t(64) << 32) |
           (uint64_t(1) << 16) | ((addr >> 4) & 0x3FFF);
}

__device__ __forceinline__ void umma(uint32_t d, uint64_t a, uint64_t b, uint32_t idesc, uint32_t en) {
    asm volatile(
        "{\n\t.reg .pred p;\n\t"
        "setp.ne.u32 p, %4, 0;\n\t"
        "tcgen05.mma.cta_group::1.kind::tf32 [%0], %1, %2, %3, {%5,%5,%5,%5}, p;\n\t}"
        :: "r"(d), "l"(a), "l"(b), "r"(idesc), "r"(en), "r"(0u) : "memory");
}

#define LDTM_X32(r, a) \
    asm volatile( \
        "tcgen05.ld.sync.aligned.32x32b.x32.b32 " \
        "{%0, %1, %2, %3, %4, %5, %6, %7, " \
        " %8, %9, %10, %11, %12, %13, %14, %15, " \
        " %16, %17, %18, %19, %20, %21, %22, %23, " \
        " %24, %25, %26, %27, %28, %29, %30, %31}, [%32];" \
        : "=r"((r)[0]),  "=r"((r)[1]),  "=r"((r)[2]),  "=r"((r)[3]), \
          "=r"((r)[4]),  "=r"((r)[5]),  "=r"((r)[6]),  "=r"((r)[7]), \
          "=r"((r)[8]),  "=r"((r)[9]),  "=r"((r)[10]), "=r"((r)[11]), \
          "=r"((r)[12]), "=r"((r)[13]), "=r"((r)[14]), "=r"((r)[15]), \
          "=r"((r)[16]), "=r"((r)[17]), "=r"((r)[18]), "=r"((r)[19]), \
          "=r"((r)[20]), "=r"((r)[21]), "=r"((r)[22]), "=r"((r)[23]), \
          "=r"((r)[24]), "=r"((r)[25]), "=r"((r)[26]), "=r"((r)[27]), \
          "=r"((r)[28]), "=r"((r)[29]), "=r"((r)[30]), "=r"((r)[31]) \
        : "r"(a))

// LDTM 32 cols of D1 starting at d1addr (this warp's 32-lane subpartition),
// rna-round to tf32, STS into S2A tile rows (tok*64 + b2base + j), col = lane.
__device__ __forceinline__ void shuffle32(uint32_t d1addr, uint32_t tilebase,
                                          int tok, int b2base, int lane) {
    uint32_t r[32];
    LDTM_X32(r, d1addr);
    TC_WAIT_LD();
    #pragma unroll
    for (int j = 0; j < 32; j++) {
        uint32_t off = (uint32_t)((tok * 64 + b2base + j) * 128 + lane * 4);
        sts32(tilebase + SWZ(off), tf32u(__uint_as_float(r[j])));
    }
}

// One K=64 r-chunk of stage 2: A = S2A buf, B = AsT tiles 2r, 2r+1.
__device__ __forceinline__ void mma_chunk(uint32_t d2, uint32_t sbase, int buf, int r, bool first) {
    #pragma unroll
    for (int s = 0; s < 8; s++) {
        uint64_t ad = sdesc(sbase + OFF_S2A + buf * 32768 + (s >> 2) * 16384) + (uint64_t)((s & 3) * 2);
        uint64_t bd = sdesc(sbase + OFF_AST + (2 * r + (s >> 2)) * 8192) + (uint64_t)((s & 3) * 2);
        umma(d2, ad, bd, IDESC2, (first && s == 0) ? 0u : 1u);
    }
}

// Stage-1 MMA: 2 N-halves x 8 K-steps.
__device__ __forceinline__ void mma_stage1(uint32_t d1, uint32_t sbase) {
    #pragma unroll
    for (int h = 0; h < 2; h++) {
        #pragma unroll
        for (int s = 0; s < 8; s++) {
            uint64_t ad = sdesc(sbase + OFF_X + (s >> 2) * 16384) + (uint64_t)((s & 3) * 2);
            uint64_t bd = sdesc(sbase + OFF_BST + (s >> 2) * 32768) + (uint64_t)(h * 1024 + (s & 3) * 2);
            umma(d1 + h * 128, ad, bd, IDESC1, (s == 0) ? 0u : 1u);
        }
    }
}

#endif // KRON_TCGEN05

__global__ void __launch_bounds__(256, 1)
kron_tc(const float* __restrict__ x, const float* __restrict__ A,
        const float* __restrict__ B, const float* __restrict__ bias,
        float* __restrict__ out, int n_tok)
{
#ifdef KRON_TCGEN05
    extern __shared__ char smc[];
    const uint32_t sbase = cvta_smem(smc);
    const int tid  = threadIdx.x;
    const int lane = tid & 31;
    const int w    = tid >> 5;
    const int q    = w & 3;     // TMEM subpartition (rows 32q..32q+31)
    const int half = w >> 2;    // column-half worker

    const uint32_t HDR = sbase + OFF_HDR;
    const uint32_t MB1 = HDR + 8, MB2 = HDR + 16, MB3 = HDR + 24;

    if (w == 0) TC_ALLOC(HDR, 512);
    if (tid == 0) { mbar_init(MB1, 1); mbar_init(MB2, 1); mbar_init(MB3, 1); }
    __syncthreads();
    uint32_t tmem;
    asm volatile("ld.shared.b32 %0, [%1];" : "=r"(tmem) : "r"(HDR));
    const uint32_t D1 = tmem;          // cols 0..255
    const uint32_t D2 = tmem + 256;    // cols 256..319

    // bias resident in registers
    float breg[16];
    #pragma unroll
    for (int m = 0; m < 16; m++) breg[m] = bias[tid + m * 256];

    // ---- Weights (tf32-rounded, SW128 K-major tiles), once per CTA ----
    // Bs'[n=(r*64+b2)][b] = B[n%4][b][n/4], split into 2 K-tiles (b-halves)
    for (int i = tid; i < 256 * 64; i += 256) {
        int n = i >> 6, b = i & 63;
        uint32_t v = tf32u(B[(n & 3) * 4096 + b * 64 + (n >> 2)]);
        sts32(sbase + OFF_BST + (b >> 5) * 32768 + SWZ((uint32_t)(n * 128 + (b & 31) * 4)), v);
    }
    // AsT[a2][k=(r*64+a)] = A[k/64][k%64][a2], split into 8 K-tiles
    for (int i = tid; i < 64 * 256; i += 256) {
        int a2 = i >> 8, k = i & 255;
        uint32_t v = tf32u(A[(k >> 6) * 4096 + (k & 63) * 64 + a2]);
        sts32(sbase + OFF_AST + (k >> 5) * 8192 + SWZ((uint32_t)(a2 * 128 + (k & 31) * 4)), v);
    }

    const int np     = n_tok >> 1;
    const int stride = gridDim.x;
    int p = blockIdx.x;

    // ---- Prologue: X(pair p) -> SMEM, issue stage-1 MMA ----
    if (p < np) {
        const float4* xin = (const float4*)(x + (size_t)p * 8192);
        #pragma unroll
        for (int t = 0; t < 8; t++) {
            int i4 = tid + t * 256;
            float4 v = xin[i4];
            int f = i4 << 2, row = f >> 6, col = f & 63;
            uint32_t addr = sbase + OFF_X + (col >> 5) * 16384 + SWZ((uint32_t)(row * 128 + (col & 31) * 4));
            sts128(addr, tf32u(v.x), tf32u(v.y), tf32u(v.z), tf32u(v.w));
        }
    }
    FENCE_ASYNC();
    __syncthreads();
    if (tid == 0 && p < np) { mma_stage1(D1, sbase); TC_COMMIT(MB1); }

    uint32_t it = 0;
    for (; p < np; p += stride, it++) {
        const uint32_t par = it & 1u;
        const int  pn      = p + stride;
        const bool hasnext = pn < np;

        // prefetch next pair's X into registers (hides LDG latency)
        float4 xr[8];
        if (hasnext) {
            const float4* xin = (const float4*)(x + (size_t)pn * 8192);
            #pragma unroll
            for (int t = 0; t < 8; t++) xr[t] = xin[tid + t * 256];
        }

        mbar_wait(MB1, par);
        TC_FENCE_AFTER();

        // ---- shuffle phase A: half0 -> D1 cols 0..63 (r=0, buf0),
        //                       half1 -> D1 cols 128..191 (r=2, buf1) ----
        {
            uint32_t tile = sbase + OFF_S2A + half * 32768 + (q & 1) * 16384;
            int tok = q >> 1;
            shuffle32(D1 + half * 128 +  0, tile, tok,  0, lane);
            shuffle32(D1 + half * 128 + 32, tile, tok, 32, lane);
        }
        // next X into X tiles (free: stage-1 MMA reads completed at MB1)
        if (hasnext) {
            #pragma unroll
            for (int t = 0; t < 8; t++) {
                int i4 = tid + t * 256, f = i4 << 2, row = f >> 6, col = f & 63;
                uint32_t addr = sbase + OFF_X + (col >> 5) * 16384 + SWZ((uint32_t)(row * 128 + (col & 31) * 4));
                sts128(addr, tf32u(xr[t].x), tf32u(xr[t].y), tf32u(xr[t].z), tf32u(xr[t].w));
            }
        }
        TC_FENCE_BEFORE();
        FENCE_ASYNC();
        __syncthreads();

        if (tid == 0) {
            mma_chunk(D2, sbase, 0, 0, true);   // K-chunk r=0 from buf0 (fresh D2)
            mma_chunk(D2, sbase, 1, 2, false);  // K-chunk r=2 from buf1
            TC_COMMIT(MB2);
        }
        mbar_wait(MB2, par);
        TC_FENCE_AFTER();

        // ---- shuffle phase B: half0 -> cols 64..127 (r=1, buf0),
        //                       half1 -> cols 192..255 (r=3, buf1) ----
        {
            uint32_t tile = sbase + OFF_S2A + half * 32768 + (q & 1) * 16384;
            int tok = q >> 1;
            shuffle32(D1 + half * 128 + 64, tile, tok,  0, lane);
            shuffle32(D1 + half * 128 + 96, tile, tok, 32, lane);
        }
        TC_FENCE_BEFORE();
        FENCE_ASYNC();
        __syncthreads();

        if (tid == 0) {
            mma_chunk(D2, sbase, 0, 1, false);  // r=1
            mma_chunk(D2, sbase, 1, 3, false);  // r=3
            TC_COMMIT(MB3);
            if (hasnext) { mma_stage1(D1, sbase); TC_COMMIT(MB1); }  // overlap next pair
        }
        mbar_wait(MB3, par);
        TC_FENCE_AFTER();

        // ---- epilogue: D2[(tok,b2)][a2] -> SMEM [tok][a2][b2] -> out ----
        {
            uint32_t r[32];
            LDTM_X32(r, D2 + half * 32);
            TC_WAIT_LD();
            int tok = q >> 1;
            int b2  = ((q & 1) << 5) + lane;
            #pragma unroll
            for (int j = 0; j < 32; j++) {
                int a2 = half * 32 + j;
                sts32(sbase + OFF_S2A + (uint32_t)(tok * 16384 + (a2 * 64 + b2) * 4), r[j]);
            }
            TC_FENCE_BEFORE();
        }
        __syncthreads();
        {
            float* orow = out + (size_t)p * 8192;
            #pragma unroll
            for (int t = 0; t < 32; t++) {
                int i = tid + t * 256;
                orow[i] = lds32f(sbase + OFF_S2A + (uint32_t)(i * 4)) + breg[t & 15];
            }
        }
        __syncthreads();  // epi staging (bufs) reused by next iteration's phase A
    }

    __syncthreads();
    if (w == 0) TC_DEALLOC(tmem, 512);

#else  // ---------- generic fallback (compute_103 PTX pass; never selected on GB300) ----------

    extern __shared__ char smc[];
    float* Bs  = (float*)smc;           // [64][256]  Bs[b][c] = B'[c][b]
    float* Asm = Bs  + 64 * 256;        // [256][64]  Asm[k][a2]
    float* T   = Asm + 256 * 64;        // [64][256]
    float* Xs  = T   + 64 * 256;        // [64][64]
    const int tid = threadIdx.x;

    for (int i = tid; i < 64 * 256; i += 256) {
        int b = i >> 8, c = i & 255;
        Bs[b * 256 + c] = __uint_as_float(tf32u(B[(c & 3) * 4096 + b * 64 + (c >> 2)]));
        int k = i >> 6, a2 = i & 63;
        Asm[k * 64 + a2] = __uint_as_float(tf32u(A[(k >> 6) * 4096 + (k & 63) * 64 + a2]));
    }
    __syncthreads();

    for (int tok = blockIdx.x; tok < n_tok; tok += gridDim.x) {
        for (int i = tid; i < 4096; i += 256)
            Xs[i] = __uint_as_float(tf32u(x[(size_t)tok * 4096 + i]));
        __syncthreads();
        for (int e = tid; e < 64 * 256; e += 256) {
            int a = e >> 8, c = e & 255;
            float s = 0.f;
            for (int b = 0; b < 64; b++) s += Xs[a * 64 + b] * Bs[b * 256 + c];
            T[a * 256 + c] = __uint_as_float(tf32u(s));
        }
        __syncthreads();
        for (int e = tid; e < 4096; e += 256) {
            int a2 = e >> 6, b2 = e & 63;
            float s = 0.f;
            for (int r = 0; r < 4; r++)
                for (int a = 0; a < 64; a++)
                    s += Asm[(r * 64 + a) * 64 + a2] * T[a * 256 + r * 64 + b2];
            out[(size_t)tok * 4096 + e] = s + bias[e];
        }
        __syncthreads();
    }
#endif
}

extern "C" void kernel_launch(void* const* d_in, const int* in_sizes, int n_in,
                              void* d_out, int out_size) {
    const float* x    = (const float*)d_in[0];
    const float* A    = (const float*)d_in[1];
    const float* B    = (const float*)d_in[2];
    const float* bias = (const float*)d_in[3];
    float* out = (float*)d_out;

    int n_tok = in_sizes[0] / 4096;
    int np = n_tok / 2;

    int dev = 0, nsm = 148;
    cudaGetDevice(&dev);
    cudaDeviceGetAttribute(&nsm, cudaDevAttrMultiProcessorCount, dev);

    cudaFuncSetAttribute(kron_tc, cudaFuncAttributeMaxDynamicSharedMemorySize, SMEM_TOTAL);

    int grid = nsm < np ? nsm : np;
    if (grid < 1) grid = 1;
    kron_tc<<<grid, 256, SMEM_TOTAL>>>(x, A, B, bias, out, n_tok);
}

// round 5
// speedup vs baseline: 2.2306x; 1.0412x over previous
#include <cuda_runtime.h>
#include <cstdint>

// ============================================================================
// KronLinear via tcgen05 (sm_103a), kind::tf32, SS-mode, TMEM accumulators.
// Software-pipelined: quarter-granular shuffle, double-buffered D2, epilogue
// deferred one pair, STG overlapped with stage-2 MMA.
//
// Per 2-token pair p:
//   Stage1: D1[(tok,a)][(r,b2)] = X(128x64) * Bs'(256x64)   (2 x N=128 MMAs)
//   Shuffle quarter r: D1 cols r*64.. -> tf32 -> S2A buf (128 rows x 64 K)
//   Stage2: D2[(tok,b2)][a2] += S2A_r(128x64) * AsT_r(64x64), r = 0..3
//   Epilogue (deferred): D2 -> SMEM transpose -> out + bias
// ============================================================================

#if defined(__CUDA_ARCH_FEAT_SM103_ALL) || defined(__CUDA_ARCH_FEAT_SM100_ALL) || \
    defined(__CUDA_ARCH_FEAT_SM101_ALL) || defined(__CUDA_ARCH_SPECIFIC__)
#define KRON_TCGEN05 1
#endif

#define OFF_X    0         // 2 K-tiles x [128 rows][32 f32] = 32KB
#define OFF_BST  32768     // 2 K-tiles x [256 rows][32 f32] = 64KB
#define OFF_AST  98304     // 8 K-tiles x [ 64 rows][32 f32] = 64KB
#define OFF_S2A  163840    // 2 bufs x 32KB (each: 2 K-tiles x [128][32])
#define OFF_STG  196608    // staging = buffer B1 (reused)
#define OFF_HDR  229376    // +0 tmem ptr, +8.. mbarriers
#define SMEM_TOTAL (229376 + 128)

#define SWZ(o) ((o) ^ (((o) >> 3) & 0x70))

// idesc: [4:6) dtype F32=1, [7:10) atype TF32=2, [10:13) btype TF32=2,
// [17:22) N>>3, [24:29) M>>4
#define IDESC1 ((1u<<4)|(2u<<7)|(2u<<10)|((128u/8)<<17)|((128u/16)<<24))   // M128 N128
#define IDESC2 ((1u<<4)|(2u<<7)|(2u<<10)|(( 64u/8)<<17)|((128u/16)<<24))   // M128 N64

__device__ __forceinline__ uint32_t cvta_smem(const void* p) {
    uint32_t a;
    asm("{ .reg .u64 t; cvta.to.shared.u64 t, %1; cvt.u32.u64 %0, t; }" : "=r"(a) : "l"(p));
    return a;
}
__device__ __forceinline__ uint32_t tf32u(float f) {
    uint32_t u; asm("cvt.rna.tf32.f32 %0, %1;" : "=r"(u) : "f"(f)); return u;
}
__device__ __forceinline__ void sts32(uint32_t a, uint32_t v) {
    asm volatile("st.shared.b32 [%0], %1;" :: "r"(a), "r"(v) : "memory");
}
__device__ __forceinline__ void sts128(uint32_t a, uint32_t x, uint32_t y, uint32_t z, uint32_t w) {
    asm volatile("st.shared.v4.b32 [%0], {%1,%2,%3,%4};" :: "r"(a), "r"(x), "r"(y), "r"(z), "r"(w) : "memory");
}
__device__ __forceinline__ float lds32f(uint32_t a) {
    float v; asm volatile("ld.shared.f32 %0, [%1];" : "=f"(v) : "r"(a)); return v;
}

#ifdef KRON_TCGEN05

__device__ __forceinline__ void mbar_init(uint32_t a, uint32_t c) {
    asm volatile("mbarrier.init.shared.b64 [%0], %1;" :: "r"(a), "r"(c) : "memory");
}
__device__ __forceinline__ void mbar_wait(uint32_t a, uint32_t parity) {
    asm volatile(
        "{\n\t.reg .pred P;\n\t"
        "WL_%=:\n\t"
        "mbarrier.try_wait.parity.acquire.cta.shared::cta.b64 P, [%0], %1, 0x989680;\n\t"
        "@P bra.uni WD_%=;\n\t"
        "bra.uni WL_%=;\n\t"
        "WD_%=:\n\t}"
        :: "r"(a), "r"(parity) : "memory");
}

#define TC_ALLOC(sa, n)   asm volatile("tcgen05.alloc.cta_group::1.sync.aligned.shared::cta.b32 [%0], %1;" :: "r"(sa), "r"((uint32_t)(n)) : "memory")
#define TC_DEALLOC(t, n)  asm volatile("tcgen05.dealloc.cta_group::1.sync.aligned.b32 %0, %1;" :: "r"(t), "r"((uint32_t)(n)))
#define TC_WAIT_LD()      asm volatile("tcgen05.wait::ld.sync.aligned;" ::: "memory")
#define TC_FENCE_BEFORE() asm volatile("tcgen05.fence::before_thread_sync;" ::: "memory")
#define TC_FENCE_AFTER()  asm volatile("tcgen05.fence::after_thread_sync;" ::: "memory")
#define TC_COMMIT(mb)     asm volatile("tcgen05.commit.cta_group::1.mbarrier::arrive::one.shared::cluster.b64 [%0];" :: "r"(mb) : "memory")
#define FENCE_ASYNC()     asm volatile("fence.proxy.async.shared::cta;" ::: "memory")

__device__ __forceinline__ uint64_t sdesc(uint32_t addr) {  // SW128, version=1, SBO=64, LBO=1
    return (uint64_t(2) << 61) | (uint64_t(1) << 46) | (uint64_t(64) << 32) |
           (uint64_t(1) << 16) | ((addr >> 4) & 0x3FFF);
}

__device__ __forceinline__ void umma(uint32_t d, uint64_t a, uint64_t b, uint32_t idesc, uint32_t en) {
    asm volatile(
        "{\n\t.reg .pred p;\n\t"
        "setp.ne.u32 p, %4, 0;\n\t"
        "tcgen05.mma.cta_group::1.kind::tf32 [%0], %1, %2, %3, {%5,%5,%5,%5}, p;\n\t}"
        :: "r"(d), "l"(a), "l"(b), "r"(idesc), "r"(en), "r"(0u) : "memory");
}

#define LDTM_X32(r, a) \
    asm volatile( \
        "tcgen05.ld.sync.aligned.32x32b.x32.b32 " \
        "{%0, %1, %2, %3, %4, %5, %6, %7, " \
        " %8, %9, %10, %11, %12, %13, %14, %15, " \
        " %16, %17, %18, %19, %20, %21, %22, %23, " \
        " %24, %25, %26, %27, %28, %29, %30, %31}, [%32];" \
        : "=r"((r)[0]),  "=r"((r)[1]),  "=r"((r)[2]),  "=r"((r)[3]), \
          "=r"((r)[4]),  "=r"((r)[5]),  "=r"((r)[6]),  "=r"((r)[7]), \
          "=r"((r)[8]),  "=r"((r)[9]),  "=r"((r)[10]), "=r"((r)[11]), \
          "=r"((r)[12]), "=r"((r)[13]), "=r"((r)[14]), "=r"((r)[15]), \
          "=r"((r)[16]), "=r"((r)[17]), "=r"((r)[18]), "=r"((r)[19]), \
          "=r"((r)[20]), "=r"((r)[21]), "=r"((r)[22]), "=r"((r)[23]), \
          "=r"((r)[24]), "=r"((r)[25]), "=r"((r)[26]), "=r"((r)[27]), \
          "=r"((r)[28]), "=r"((r)[29]), "=r"((r)[30]), "=r"((r)[31]) \
        : "r"(a))

// Shuffle quarter r: all 8 warps. Warp (q,half) reads D1 cols r*64 + 32*half
// (its 32-lane subpartition), writes S2A buf rows (q>>1)*64 + 32*half + j,
// K-tile (q&1), K-col = lane. Conflict-free (full 128B row segments).
__device__ __forceinline__ void shuffleQ(uint32_t d1col, uint32_t bufbase,
                                         int q, int half, int lane) {
    uint32_t r[32];
    LDTM_X32(r, d1col);
    TC_WAIT_LD();
    uint32_t tile = bufbase + (uint32_t)((q & 1) * 16384);
    int row0 = (q >> 1) * 64 + 32 * half;
    #pragma unroll
    for (int j = 0; j < 32; j++) {
        uint32_t off = (uint32_t)((row0 + j) * 128 + lane * 4);
        sts32(tile + SWZ(off), tf32u(__uint_as_float(r[j])));
    }
}

// One K=64 r-chunk of stage 2: A = S2A buf, B = AsT tiles 2r, 2r+1.
__device__ __forceinline__ void mma_chunk(uint32_t d2, uint32_t sbase, int buf, int r, bool first) {
    #pragma unroll
    for (int s = 0; s < 8; s++) {
        uint64_t ad = sdesc(sbase + OFF_S2A + buf * 32768 + (s >> 2) * 16384) + (uint64_t)((s & 3) * 2);
        uint64_t bd = sdesc(sbase + OFF_AST + (2 * r + (s >> 2)) * 8192) + (uint64_t)((s & 3) * 2);
        umma(d2, ad, bd, IDESC2, (first && s == 0) ? 0u : 1u);
    }
}

// Stage-1 MMA: 2 N-halves x 8 K-steps.
__device__ __forceinline__ void mma_stage1(uint32_t d1, uint32_t sbase) {
    #pragma unroll
    for (int h = 0; h < 2; h++) {
        #pragma unroll
        for (int s = 0; s < 8; s++) {
            uint64_t ad = sdesc(sbase + OFF_X + (s >> 2) * 16384) + (uint64_t)((s & 3) * 2);
            uint64_t bd = sdesc(sbase + OFF_BST + (s >> 2) * 32768) + (uint64_t)(h * 1024 + (s & 3) * 2);
            umma(d1 + h * 128, ad, bd, IDESC1, (s == 0) ? 0u : 1u);
        }
    }
}

// X (token pair) registers -> swizzled X tiles in SMEM
__device__ __forceinline__ void store_x(uint32_t sbase, const float4* xr, int tid) {
    #pragma unroll
    for (int t = 0; t < 8; t++) {
        int i4 = tid + t * 256, f = i4 << 2, row = f >> 6, col = f & 63;
        uint32_t addr = sbase + OFF_X + (col >> 5) * 16384 + SWZ((uint32_t)(row * 128 + (col & 31) * 4));
        sts128(addr, tf32u(xr[t].x), tf32u(xr[t].y), tf32u(xr[t].z), tf32u(xr[t].w));
    }
}

#endif // KRON_TCGEN05

__global__ void __launch_bounds__(256, 1)
kron_tc(const float* __restrict__ x, const float* __restrict__ A,
        const float* __restrict__ B, const float* __restrict__ bias,
        float* __restrict__ out, int n_tok)
{
#ifdef KRON_TCGEN05
    extern __shared__ char smc[];
    const uint32_t sbase = cvta_smem(smc);
    const int tid  = threadIdx.x;
    const int lane = tid & 31;
    const int w    = tid >> 5;
    const int q    = w & 3;     // TMEM subpartition
    const int half = w >> 2;    // column-half worker

    const uint32_t HDR = sbase + OFF_HDR;
    const uint32_t MBa = HDR + 8, MBc0 = HDR + 16, MBc1 = HDR + 24, MBd = HDR + 32;
    const uint32_t B0 = sbase + OFF_S2A, B1 = sbase + OFF_S2A + 32768;
    const uint32_t STGB = sbase + OFF_STG;   // == B1

    if (w == 0) TC_ALLOC(HDR, 512);
    if (tid == 0) { mbar_init(MBa, 1); mbar_init(MBc0, 1); mbar_init(MBc1, 1); mbar_init(MBd, 1); }
    __syncthreads();
    uint32_t tmem;
    asm volatile("ld.shared.b32 %0, [%1];" : "=r"(tmem) : "r"(HDR));
    const uint32_t D1 = tmem;          // cols 0..255
    const uint32_t D2B = tmem + 256;   // 2 bufs x 64 cols

    // bias resident in registers
    float breg[16];
    #pragma unroll
    for (int m = 0; m < 16; m++) breg[m] = bias[tid + m * 256];

    // ---- Weights (tf32-rounded, SW128 K-major tiles), once per CTA ----
    for (int i = tid; i < 256 * 64; i += 256) {
        int n = i >> 6, b = i & 63;
        uint32_t v = tf32u(B[(n & 3) * 4096 + b * 64 + (n >> 2)]);
        sts32(sbase + OFF_BST + (b >> 5) * 32768 + SWZ((uint32_t)(n * 128 + (b & 31) * 4)), v);
    }
    for (int i = tid; i < 64 * 256; i += 256) {
        int a2 = i >> 8, k = i & 255;
        uint32_t v = tf32u(A[(k >> 6) * 4096 + (k & 63) * 64 + a2]);
        sts32(sbase + OFF_AST + (k >> 5) * 8192 + SWZ((uint32_t)(a2 * 128 + (k & 31) * 4)), v);
    }

    const int np     = n_tok >> 1;
    const int stride = gridDim.x;
    int p = blockIdx.x;

    // ---- Prologue: X(p) -> SMEM, issue stage-1, commit MBa ----
    if (p < np) {
        const float4* xin = (const float4*)(x + (size_t)p * 8192);
        float4 xr[8];
        #pragma unroll
        for (int t = 0; t < 8; t++) xr[t] = xin[tid + t * 256];
        store_x(sbase, xr, tid);
    }
    FENCE_ASYNC();
    __syncthreads();
    if (tid == 0 && p < np) { mma_stage1(D1, sbase); TC_COMMIT(MBa); }

    int it = 0;
    int p_prev = -1;
    for (; p < np; p += stride, it++) {
        const uint32_t par = (uint32_t)(it & 1);
        const int  pn      = p + stride;
        const bool hasnext = pn < np;

        // prefetch next pair's X
        float4 xr[8];
        if (hasnext) {
            const float4* xin = (const float4*)(x + (size_t)pn * 8192);
            #pragma unroll
            for (int t = 0; t < 8; t++) xr[t] = xin[tid + t * 256];
        }

        // ---- deferred epilogue part 1: D2(prev) -> staging (B1) ----
        if (it > 0) {
            mbar_wait(MBd, par ^ 1u);    // stage2(prev) done (usually 0 wait)
            TC_FENCE_AFTER();
            uint32_t r[32];
            LDTM_X32(r, D2B + 64 * (par ^ 1u) + 32 * half);
            TC_WAIT_LD();
            int tok = q >> 1, b2 = (q & 1) * 32 + lane;
            #pragma unroll
            for (int j = 0; j < 32; j++) {
                int a2 = 32 * half + j;
                sts32(STGB + (uint32_t)(tok * 16384 + (a2 * 64 + b2) * 4), r[j]);
            }
        }

        // ---- shuffle r0 -> B0 (stage1(p) results) ----
        mbar_wait(MBa, par);
        TC_FENCE_AFTER();
        shuffleQ(D1 + 0 * 64 + 32 * half, B0, q, half, lane);
        if (hasnext) store_x(sbase, xr, tid);   // X free after MBa
        TC_FENCE_BEFORE();
        FENCE_ASYNC();
        __syncthreads();

        const uint32_t d2 = D2B + 64 * par;
        if (tid == 0) { mma_chunk(d2, sbase, 0, 0, true); TC_COMMIT(MBc0); }

        // ---- epilogue part 2: STG prev pair (overlaps stage-2 r0 MMA) ----
        if (it > 0) {
            float* orow = out + (size_t)p_prev * 8192;
            #pragma unroll
            for (int t = 0; t < 32; t++) {
                int i = tid + t * 256;
                orow[i] = lds32f(STGB + (uint32_t)(i * 4)) + breg[t & 15];
            }
        }
        __syncthreads();                        // staging (B1) free for r1

        // ---- shuffle r1 -> B1 ----
        shuffleQ(D1 + 1 * 64 + 32 * half, B1, q, half, lane);
        TC_FENCE_BEFORE();
        FENCE_ASYNC();
        __syncthreads();
        if (tid == 0) { mma_chunk(d2, sbase, 1, 1, false); TC_COMMIT(MBc1); }

        // ---- shuffle r2 -> B0 (after r0 chunk done reading it) ----
        mbar_wait(MBc0, par);
        shuffleQ(D1 + 2 * 64 + 32 * half, B0, q, half, lane);
        TC_FENCE_BEFORE();
        FENCE_ASYNC();
        __syncthreads();
        if (tid == 0) { mma_chunk(d2, sbase, 0, 2, false); }  // covered by MBd

        // ---- shuffle r3 -> B1 (after r1 chunk done) ----
        mbar_wait(MBc1, par);
        shuffleQ(D1 + 3 * 64 + 32 * half, B1, q, half, lane);
        TC_FENCE_BEFORE();
        FENCE_ASYNC();
        __syncthreads();
        if (tid == 0) {
            mma_chunk(d2, sbase, 1, 3, false);
            TC_COMMIT(MBd);                      // covers r2 + r3 (in-order)
            if (hasnext) { mma_stage1(D1, sbase); TC_COMMIT(MBa); }
        }
        p_prev = p;
    }

    // ---- final epilogue ----
    if (p_prev >= 0) {
        const uint32_t lpar = (uint32_t)((it - 1) & 1);
        mbar_wait(MBd, lpar);
        TC_FENCE_AFTER();
        uint32_t r[32];
        LDTM_X32(r, D2B + 64 * lpar + 32 * half);
        TC_WAIT_LD();
        int tok = q >> 1, b2 = (q & 1) * 32 + lane;
        #pragma unroll
        for (int j = 0; j < 32; j++) {
            int a2 = 32 * half + j;
            sts32(STGB + (uint32_t)(tok * 16384 + (a2 * 64 + b2) * 4), r[j]);
        }
        __syncthreads();
        float* orow = out + (size_t)p_prev * 8192;
        #pragma unroll
        for (int t = 0; t < 32; t++) {
            int i = tid + t * 256;
            orow[i] = lds32f(STGB + (uint32_t)(i * 4)) + breg[t & 15];
        }
    }

    __syncthreads();
    if (w == 0) TC_DEALLOC(tmem, 512);

#else  // ---------- generic fallback (compute_103 PTX pass; never selected on GB300) ----------

    extern __shared__ char smc[];
    float* Bs  = (float*)smc;           // [64][256]
    float* Asm = Bs  + 64 * 256;        // [256][64]
    float* T   = Asm + 256 * 64;        // [64][256]
    float* Xs  = T   + 64 * 256;        // [64][64]
    const int tid = threadIdx.x;

    for (int i = tid; i < 64 * 256; i += 256) {
        int b = i >> 8, c = i & 255;
        Bs[b * 256 + c] = __uint_as_float(tf32u(B[(c & 3) * 4096 + b * 64 + (c >> 2)]));
        int k = i >> 6, a2 = i & 63;
        Asm[k * 64 + a2] = __uint_as_float(tf32u(A[(k >> 6) * 4096 + (k & 63) * 64 + a2]));
    }
    __syncthreads();

    for (int tok = blockIdx.x; tok < n_tok; tok += gridDim.x) {
        for (int i = tid; i < 4096; i += 256)
            Xs[i] = __uint_as_float(tf32u(x[(size_t)tok * 4096 + i]));
        __syncthreads();
        for (int e = tid; e < 64 * 256; e += 256) {
            int a = e >> 8, c = e & 255;
            float s = 0.f;
            for (int b = 0; b < 64; b++) s += Xs[a * 64 + b] * Bs[b * 256 + c];
            T[a * 256 + c] = __uint_as_float(tf32u(s));
        }
        __syncthreads();
        for (int e = tid; e < 4096; e += 256) {
            int a2 = e >> 6, b2 = e & 63;
            float s = 0.f;
            for (int r = 0; r < 4; r++)
                for (int a = 0; a < 64; a++)
                    s += Asm[(r * 64 + a) * 64 + a2] * T[a * 256 + r * 64 + b2];
            out[(size_t)tok * 4096 + e] = s + bias[e];
        }
        __syncthreads();
    }
#endif
}

extern "C" void kernel_launch(void* const* d_in, const int* in_sizes, int n_in,
                              void* d_out, int out_size) {
    const float* x    = (const float*)d_in[0];
    const float* A    = (const float*)d_in[1];
    const float* B    = (const float*)d_in[2];
    const float* bias = (const float*)d_in[3];
    float* out = (float*)d_out;

    int n_tok = in_sizes[0] / 4096;
    int np = n_tok / 2;

    int dev = 0, nsm = 148;
    cudaGetDevice(&dev);
    cudaDeviceGetAttribute(&nsm, cudaDevAttrMultiProcessorCount, dev);

    cudaFuncSetAttribute(kron_tc, cudaFuncAttributeMaxDynamicSharedMemorySize, SMEM_TOTAL);

    int grid = nsm < np ? nsm : np;
    if (grid < 1) grid = 1;
    kron_tc<<<grid, 256, SMEM_TOTAL>>>(x, A, B, bias, out, n_tok);
}

// round 6
// speedup vs baseline: 2.9734x; 1.3330x over previous
#include <cuda_runtime.h>
#include <cstdint>

// ============================================================================
// KronLinear via tcgen05 (sm_103a), kind::tf32, SS-mode, TMEM accumulators.
// R6: 512 threads (16 warps), half-granular shuffle (1 LDTM.x32/warp/half),
// direct-register STG epilogue with register bias, split MBc barriers.
//
// Per 2-token pair p:
//   Stage1: D1[(tok,a)][(r,b2)] = X(128x64) * Bs'(256x64)   (2 x N=128 MMAs)
//   Shuffle half h: D1 cols 128h.. -> tf32 -> S2A bufs B0,B1 (2 r-chunks)
//   Stage2: D2[(tok,b2)][a2] += S2A_r(128x64) * AsT_r(64x64), r = 0..3
//   Epilogue (deferred 1 pair): D2 -> registers -> +bias -> coalesced STG
// ============================================================================

#if defined(__CUDA_ARCH_FEAT_SM103_ALL) || defined(__CUDA_ARCH_FEAT_SM100_ALL) || \
    defined(__CUDA_ARCH_FEAT_SM101_ALL) || defined(__CUDA_ARCH_SPECIFIC__)
#define KRON_TCGEN05 1
#endif

#define NTHREADS 512

#define OFF_X    0         // 2 K-tiles x [128 rows][32 f32] = 32KB
#define OFF_BST  32768     // 2 K-tiles x [256 rows][32 f32] = 64KB
#define OFF_AST  98304     // 8 K-tiles x [ 64 rows][32 f32] = 64KB
#define OFF_S2A  163840    // 2 bufs x 32KB (each: 2 K-tiles x [128][32])
#define OFF_HDR  229376    // +0 tmem ptr, +8.. mbarriers
#define SMEM_TOTAL (229376 + 128)

#define SWZ(o) ((o) ^ (((o) >> 3) & 0x70))

// idesc: [4:6) dtype F32=1, [7:10) atype TF32=2, [10:13) btype TF32=2,
// [17:22) N>>3, [24:29) M>>4
#define IDESC1 ((1u<<4)|(2u<<7)|(2u<<10)|((128u/8)<<17)|((128u/16)<<24))   // M128 N128
#define IDESC2 ((1u<<4)|(2u<<7)|(2u<<10)|(( 64u/8)<<17)|((128u/16)<<24))   // M128 N64

__device__ __forceinline__ uint32_t cvta_smem(const void* p) {
    uint32_t a;
    asm("{ .reg .u64 t; cvta.to.shared.u64 t, %1; cvt.u32.u64 %0, t; }" : "=r"(a) : "l"(p));
    return a;
}
__device__ __forceinline__ uint32_t tf32u(float f) {
    uint32_t u; asm("cvt.rna.tf32.f32 %0, %1;" : "=r"(u) : "f"(f)); return u;
}
__device__ __forceinline__ void sts32(uint32_t a, uint32_t v) {
    asm volatile("st.shared.b32 [%0], %1;" :: "r"(a), "r"(v) : "memory");
}
__device__ __forceinline__ void sts128(uint32_t a, uint32_t x, uint32_t y, uint32_t z, uint32_t w) {
    asm volatile("st.shared.v4.b32 [%0], {%1,%2,%3,%4};" :: "r"(a), "r"(x), "r"(y), "r"(z), "r"(w) : "memory");
}

#ifdef KRON_TCGEN05

__device__ __forceinline__ void mbar_init(uint32_t a, uint32_t c) {
    asm volatile("mbarrier.init.shared.b64 [%0], %1;" :: "r"(a), "r"(c) : "memory");
}
__device__ __forceinline__ void mbar_wait(uint32_t a, uint32_t parity) {
    asm volatile(
        "{\n\t.reg .pred P;\n\t"
        "WL_%=:\n\t"
        "mbarrier.try_wait.parity.acquire.cta.shared::cta.b64 P, [%0], %1, 0x989680;\n\t"
        "@P bra.uni WD_%=;\n\t"
        "bra.uni WL_%=;\n\t"
        "WD_%=:\n\t}"
        :: "r"(a), "r"(parity) : "memory");
}

#define TC_ALLOC(sa, n)   asm volatile("tcgen05.alloc.cta_group::1.sync.aligned.shared::cta.b32 [%0], %1;" :: "r"(sa), "r"((uint32_t)(n)) : "memory")
#define TC_DEALLOC(t, n)  asm volatile("tcgen05.dealloc.cta_group::1.sync.aligned.b32 %0, %1;" :: "r"(t), "r"((uint32_t)(n)))
#define TC_WAIT_LD()      asm volatile("tcgen05.wait::ld.sync.aligned;" ::: "memory")
#define TC_FENCE_BEFORE() asm volatile("tcgen05.fence::before_thread_sync;" ::: "memory")
#define TC_FENCE_AFTER()  asm volatile("tcgen05.fence::after_thread_sync;" ::: "memory")
#define TC_COMMIT(mb)     asm volatile("tcgen05.commit.cta_group::1.mbarrier::arrive::one.shared::cluster.b64 [%0];" :: "r"(mb) : "memory")
#define FENCE_ASYNC()     asm volatile("fence.proxy.async.shared::cta;" ::: "memory")

__device__ __forceinline__ uint64_t sdesc(uint32_t addr) {  // SW128, version=1, SBO=64, LBO=1
    return (uint64_t(2) << 61) | (uint64_t(1) << 46) | (uint64_t(64) << 32) |
           (uint64_t(1) << 16) | ((addr >> 4) & 0x3FFF);
}

__device__ __forceinline__ void umma(uint32_t d, uint64_t a, uint64_t b, uint32_t idesc, uint32_t en) {
    asm volatile(
        "{\n\t.reg .pred p;\n\t"
        "setp.ne.u32 p, %4, 0;\n\t"
        "tcgen05.mma.cta_group::1.kind::tf32 [%0], %1, %2, %3, {%5,%5,%5,%5}, p;\n\t}"
        :: "r"(d), "l"(a), "l"(b), "r"(idesc), "r"(en), "r"(0u) : "memory");
}

#define LDTM_X32(r, a) \
    asm volatile( \
        "tcgen05.ld.sync.aligned.32x32b.x32.b32 " \
        "{%0, %1, %2, %3, %4, %5, %6, %7, " \
        " %8, %9, %10, %11, %12, %13, %14, %15, " \
        " %16, %17, %18, %19, %20, %21, %22, %23, " \
        " %24, %25, %26, %27, %28, %29, %30, %31}, [%32];" \
        : "=r"((r)[0]),  "=r"((r)[1]),  "=r"((r)[2]),  "=r"((r)[3]), \
          "=r"((r)[4]),  "=r"((r)[5]),  "=r"((r)[6]),  "=r"((r)[7]), \
          "=r"((r)[8]),  "=r"((r)[9]),  "=r"((r)[10]), "=r"((r)[11]), \
          "=r"((r)[12]), "=r"((r)[13]), "=r"((r)[14]), "=r"((r)[15]), \
          "=r"((r)[16]), "=r"((r)[17]), "=r"((r)[18]), "=r"((r)[19]), \
          "=r"((r)[20]), "=r"((r)[21]), "=r"((r)[22]), "=r"((r)[23]), \
          "=r"((r)[24]), "=r"((r)[25]), "=r"((r)[26]), "=r"((r)[27]), \
          "=r"((r)[28]), "=r"((r)[29]), "=r"((r)[30]), "=r"((r)[31]) \
        : "r"(a))

#define LDTM_X16(r, a) \
    asm volatile( \
        "tcgen05.ld.sync.aligned.32x32b.x16.b32 " \
        "{%0, %1, %2, %3, %4, %5, %6, %7, " \
        " %8, %9, %10, %11, %12, %13, %14, %15}, [%16];" \
        : "=r"((r)[0]),  "=r"((r)[1]),  "=r"((r)[2]),  "=r"((r)[3]), \
          "=r"((r)[4]),  "=r"((r)[5]),  "=r"((r)[6]),  "=r"((r)[7]), \
          "=r"((r)[8]),  "=r"((r)[9]),  "=r"((r)[10]), "=r"((r)[11]), \
          "=r"((r)[12]), "=r"((r)[13]), "=r"((r)[14]), "=r"((r)[15]) \
        : "r"(a))

// Shuffle half h: warp (c = w>>2, q = w&3) reads D1 cols 128h + 32c .. +32
// (its 32-lane subpartition, lanes = (tok,a)), writes S2A buffer (c>>1),
// rows (q>>1)*64 + (c&1)*32 + j, K-tile (q&1), K-col = lane. Conflict-free.
__device__ __forceinline__ void shuffleH(uint32_t d1col, uint32_t sbase,
                                         int c, int q, int lane) {
    uint32_t r[32];
    LDTM_X32(r, d1col);
    TC_WAIT_LD();
    uint32_t tile = sbase + OFF_S2A + (uint32_t)((c >> 1) * 32768 + (q & 1) * 16384);
    int row0 = (q >> 1) * 64 + (c & 1) * 32;
    #pragma unroll
    for (int j = 0; j < 32; j++) {
        uint32_t off = (uint32_t)((row0 + j) * 128 + lane * 4);
        sts32(tile + SWZ(off), tf32u(__uint_as_float(r[j])));
    }
}

// One K=64 r-chunk of stage 2: A = S2A buf, B = AsT tiles 2r, 2r+1.
__device__ __forceinline__ void mma_chunk(uint32_t d2, uint32_t sbase, int buf, int r, bool first) {
    #pragma unroll
    for (int s = 0; s < 8; s++) {
        uint64_t ad = sdesc(sbase + OFF_S2A + buf * 32768 + (s >> 2) * 16384) + (uint64_t)((s & 3) * 2);
        uint64_t bd = sdesc(sbase + OFF_AST + (2 * r + (s >> 2)) * 8192) + (uint64_t)((s & 3) * 2);
        umma(d2, ad, bd, IDESC2, (first && s == 0) ? 0u : 1u);
    }
}

// Stage-1 MMA: 2 N-halves x 8 K-steps.
__device__ __forceinline__ void mma_stage1(uint32_t d1, uint32_t sbase) {
    #pragma unroll
    for (int h = 0; h < 2; h++) {
        #pragma unroll
        for (int s = 0; s < 8; s++) {
            uint64_t ad = sdesc(sbase + OFF_X + (s >> 2) * 16384) + (uint64_t)((s & 3) * 2);
            uint64_t bd = sdesc(sbase + OFF_BST + (s >> 2) * 32768) + (uint64_t)(h * 1024 + (s & 3) * 2);
            umma(d1 + h * 128, ad, bd, IDESC1, (s == 0) ? 0u : 1u);
        }
    }
}

// X (token pair) registers -> swizzled X tiles in SMEM (512 threads, 4 vec4)
__device__ __forceinline__ void store_x(uint32_t sbase, const float4* xr, int tid) {
    #pragma unroll
    for (int t = 0; t < 4; t++) {
        int i4 = tid + t * NTHREADS, f = i4 << 2, row = f >> 6, col = f & 63;
        uint32_t addr = sbase + OFF_X + (col >> 5) * 16384 + SWZ((uint32_t)(row * 128 + (col & 31) * 4));
        sts128(addr, tf32u(xr[t].x), tf32u(xr[t].y), tf32u(xr[t].z), tf32u(xr[t].w));
    }
}

#endif // KRON_TCGEN05

__global__ void __launch_bounds__(NTHREADS, 1)
kron_tc(const float* __restrict__ x, const float* __restrict__ A,
        const float* __restrict__ B, const float* __restrict__ bias,
        float* __restrict__ out, int n_tok)
{
#ifdef KRON_TCGEN05
    extern __shared__ char smc[];
    const uint32_t sbase = cvta_smem(smc);
    const int tid  = threadIdx.x;
    const int lane = tid & 31;
    const int w    = tid >> 5;
    const int q    = w & 3;     // TMEM subpartition (lanes 32q..32q+31)
    const int c    = w >> 2;    // column-group worker 0..3

    const uint32_t HDR = sbase + OFF_HDR;
    const uint32_t MBa = HDR + 8, MBc0 = HDR + 16, MBc1 = HDR + 24, MBd = HDR + 32;

    if (w == 0) TC_ALLOC(HDR, 512);
    if (tid == 0) { mbar_init(MBa, 1); mbar_init(MBc0, 1); mbar_init(MBc1, 1); mbar_init(MBd, 1); }
    __syncthreads();
    uint32_t tmem;
    asm volatile("ld.shared.b32 %0, [%1];" : "=r"(tmem) : "r"(HDR));
    const uint32_t D1 = tmem;          // cols 0..255
    const uint32_t D2B = tmem + 256;   // 2 bufs x 64 cols

    // per-thread epilogue bias: bj[j] = bias[a2*64 + b2], a2 = 16c+j, b2 = (q&1)*32+lane
    const int b2me = (q & 1) * 32 + lane;
    const int tokme = q >> 1;
    float bj[16];
    #pragma unroll
    for (int j = 0; j < 16; j++) bj[j] = bias[(16 * c + j) * 64 + b2me];

    // ---- Weights (tf32-rounded, SW128 K-major tiles), once per CTA ----
    for (int i = tid; i < 256 * 64; i += NTHREADS) {
        int n = i >> 6, b = i & 63;
        uint32_t v = tf32u(B[(n & 3) * 4096 + b * 64 + (n >> 2)]);
        sts32(sbase + OFF_BST + (b >> 5) * 32768 + SWZ((uint32_t)(n * 128 + (b & 31) * 4)), v);
    }
    for (int i = tid; i < 64 * 256; i += NTHREADS) {
        int a2 = i >> 8, k = i & 255;
        uint32_t v = tf32u(A[(k >> 6) * 4096 + (k & 63) * 64 + a2]);
        sts32(sbase + OFF_AST + (k >> 5) * 8192 + SWZ((uint32_t)(a2 * 128 + (k & 31) * 4)), v);
    }

    const int np     = n_tok >> 1;
    const int stride = gridDim.x;
    int p = blockIdx.x;

    // ---- Prologue: X(p) -> SMEM, issue stage-1, commit MBa ----
    if (p < np) {
        const float4* xin = (const float4*)(x + (size_t)p * 8192);
        float4 xr[4];
        #pragma unroll
        for (int t = 0; t < 4; t++) xr[t] = xin[tid + t * NTHREADS];
        store_x(sbase, xr, tid);
    }
    FENCE_ASYNC();
    __syncthreads();
    if (tid == 0 && p < np) { mma_stage1(D1, sbase); TC_COMMIT(MBa); }

    int it = 0;
    int p_prev = -1;
    for (; p < np; p += stride, it++) {
        const uint32_t par = (uint32_t)(it & 1);
        const int  pn      = p + stride;
        const bool hasnext = pn < np;

        // prefetch next pair's X (LDGs in flight under everything below)
        float4 xr[4];
        if (hasnext) {
            const float4* xin = (const float4*)(x + (size_t)pn * 8192);
            #pragma unroll
            for (int t = 0; t < 4; t++) xr[t] = xin[tid + t * NTHREADS];
        }

        // ---- deferred epilogue: D2(prev) -> regs -> +bias -> coalesced STG ----
        if (it > 0) {
            mbar_wait(MBd, par ^ 1u);    // stage2(prev) chunks r2,r3 done
            TC_FENCE_AFTER();
            uint32_t r[16];
            LDTM_X16(r, D2B + 64 * (par ^ 1u) + 16 * c);
            TC_WAIT_LD();
            float* orow = out + (size_t)p_prev * 8192 + tokme * 4096 + b2me;
            #pragma unroll
            for (int j = 0; j < 16; j++)
                orow[(16 * c + j) * 64] = __uint_as_float(r[j]) + bj[j];
            TC_FENCE_BEFORE();
        }

        // ---- shuffle half 0 (r-chunks 0,1) ----
        mbar_wait(MBa, par);             // stage1(p) done
        TC_FENCE_AFTER();
        shuffleH(D1 + 32 * c, sbase, c, q, lane);
        if (hasnext) store_x(sbase, xr, tid);   // X tiles free after MBa
        TC_FENCE_BEFORE();
        FENCE_ASYNC();
        __syncthreads();

        const uint32_t d2 = D2B + 64 * par;
        if (tid == 0) {
            mma_chunk(d2, sbase, 0, 0, true);  TC_COMMIT(MBc0);
            mma_chunk(d2, sbase, 1, 1, false); TC_COMMIT(MBc1);
        }

        // ---- shuffle half 1 (r-chunks 2,3); B0 writers wait MBc0, B1 writers MBc1 ----
        mbar_wait((c >> 1) ? MBc1 : MBc0, par);
        shuffleH(D1 + 128 + 32 * c, sbase, c, q, lane);
        TC_FENCE_BEFORE();
        FENCE_ASYNC();
        __syncthreads();

        if (tid == 0) {
            mma_chunk(d2, sbase, 0, 2, false);
            mma_chunk(d2, sbase, 1, 3, false);
            TC_COMMIT(MBd);
            if (hasnext) { mma_stage1(D1, sbase); TC_COMMIT(MBa); }
        }
        p_prev = p;
    }

    // ---- final epilogue ----
    if (p_prev >= 0) {
        const uint32_t lpar = (uint32_t)((it - 1) & 1);
        mbar_wait(MBd, lpar);
        TC_FENCE_AFTER();
        uint32_t r[16];
        LDTM_X16(r, D2B + 64 * lpar + 16 * c);
        TC_WAIT_LD();
        float* orow = out + (size_t)p_prev * 8192 + tokme * 4096 + b2me;
        #pragma unroll
        for (int j = 0; j < 16; j++)
            orow[(16 * c + j) * 64] = __uint_as_float(r[j]) + bj[j];
    }

    __syncthreads();
    if (w == 0) TC_DEALLOC(tmem, 512);

#else  // ---------- generic fallback (compute_103 PTX pass; never selected on GB300) ----------

    extern __shared__ char smc[];
    float* Bs  = (float*)smc;           // [64][256]
    float* Asm = Bs  + 64 * 256;        // [256][64]
    float* T   = Asm + 256 * 64;        // [64][256]
    float* Xs  = T   + 64 * 256;        // [64][64]
    const int tid = threadIdx.x;

    for (int i = tid; i < 64 * 256; i += NTHREADS) {
        int b = i >> 8, cc = i & 255;
        Bs[b * 256 + cc] = __uint_as_float(tf32u(B[(cc & 3) * 4096 + b * 64 + (cc >> 2)]));
        int k = i >> 6, a2 = i & 63;
        Asm[k * 64 + a2] = __uint_as_float(tf32u(A[(k >> 6) * 4096 + (k & 63) * 64 + a2]));
    }
    __syncthreads();

    for (int tok = blockIdx.x; tok < n_tok; tok += gridDim.x) {
        for (int i = tid; i < 4096; i += NTHREADS)
            Xs[i] = __uint_as_float(tf32u(x[(size_t)tok * 4096 + i]));
        __syncthreads();
        for (int e = tid; e < 64 * 256; e += NTHREADS) {
            int a = e >> 8, cc = e & 255;
            float s = 0.f;
            for (int b = 0; b < 64; b++) s += Xs[a * 64 + b] * Bs[b * 256 + cc];
            T[a * 256 + cc] = __uint_as_float(tf32u(s));
        }
        __syncthreads();
        for (int e = tid; e < 4096; e += NTHREADS) {
            int a2 = e >> 6, b2 = e & 63;
            float s = 0.f;
            for (int r = 0; r < 4; r++)
                for (int a = 0; a < 64; a++)
                    s += Asm[(r * 64 + a) * 64 + a2] * T[a * 256 + r * 64 + b2];
            out[(size_t)tok * 4096 + e] = s + bias[e];
        }
        __syncthreads();
    }
#endif
}

extern "C" void kernel_launch(void* const* d_in, const int* in_sizes, int n_in,
                              void* d_out, int out_size) {
    const float* x    = (const float*)d_in[0];
    const float* A    = (const float*)d_in[1];
    const float* B    = (const float*)d_in[2];
    const float* bias = (const float*)d_in[3];
    float* out = (float*)d_out;

    int n_tok = in_sizes[0] / 4096;
    int np = n_tok / 2;

    int dev = 0, nsm = 148;
    cudaGetDevice(&dev);
    cudaDeviceGetAttribute(&nsm, cudaDevAttrMultiProcessorCount, dev);

    cudaFuncSetAttribute(kron_tc, cudaFuncAttributeMaxDynamicSharedMemorySize, SMEM_TOTAL);

    int grid = nsm < np ? nsm : np;
    if (grid < 1) grid = 1;
    kron_tc<<<grid, NTHREADS, SMEM_TOTAL>>>(x, A, B, bias, out, n_tok);
}